// round 17
// baseline (speedup 1.0000x reference)
#include <cuda_runtime.h>

typedef unsigned long long ull;

constexpr int BS = 16384, D = 100, H = 16, P = 2;
constexpr int DD = D * D;
constexpr int TB_B = 64;      // batch per block (8 warps x 8 b-per-thread)
constexpr int TB_T = 8;       // t per block
constexpr int NTH  = 256;     // 8 warps
constexpr int W0S  = 1616;    // sW0 row stride floats
constexpr int W1S  = 260;
constexpr int HS_I = 65;      // sH0 i-stride (padded)
constexpr int HS_T = 16 * HS_I;

// smem map (float offsets)
constexpr int OFF_W0 = 0;                        // 8*1616 = 12928 (overlaid by sH0)
constexpr int OFF_X  = OFF_W0 + 8 * W0S;         // 12928 ; 6400
constexpr int OFF_W1 = OFF_X  + 6400;            // 19328 ; 2080
constexpr int OFF_B1 = OFF_W1 + 8 * W1S;         // 21408 ; 144
constexpr int OFF_W2 = OFF_B1 + 144;             // 21552 ; 288
constexpr int OFF_B2 = OFF_W2 + 288;             // 21840 ; 16
constexpr int OFF_MR = OFF_B2 + 16;              // 21856 ; ring: 8 warps*8 stages*64
constexpr int SMEM_FLOATS = OFF_MR + 8 * 8 * 64; // 25952 -> 103808 B (2 CTA/SM)

__device__ __forceinline__ ull pk2(float a, float b) {
    ull r; asm("mov.b64 %0, {%1, %2};" : "=l"(r) : "f"(a), "f"(b)); return r;
}
__device__ __forceinline__ void unpk2(ull v, float& a, float& b) {
    asm("mov.b64 {%0, %1}, %2;" : "=f"(a), "=f"(b) : "l"(v));
}
__device__ __forceinline__ ull ffma2(ull a, ull b, ull c) {
    ull d; asm("fma.rn.f32x2 %0, %1, %2, %3;" : "=l"(d) : "l"(a), "l"(b), "l"(c));
    return d;
}
__device__ __forceinline__ float lrelu(float v) { return v > 0.f ? v : 0.01f * v; }
__device__ __forceinline__ unsigned smem_u32(const void* p) {
    unsigned a;
    asm("{ .reg .u64 t; cvta.to.shared.u64 t, %1; cvt.u32.u64 %0, t; }" : "=r"(a) : "l"(p));
    return a;
}

__global__ void __launch_bounds__(NTH, 2)
mlp_kernel(const float* __restrict__ xg, const float* __restrict__ M,
           const float* __restrict__ W0g, const float* __restrict__ W1g,
           const float* __restrict__ W2g, const float* __restrict__ b0g,
           const float* __restrict__ b1g, const float* __restrict__ b2g,
           float* __restrict__ out) {
    extern __shared__ float smem[];
    float* sW0 = smem + OFF_W0;
    float* sH0 = smem + OFF_W0;     // overlays sW0 after mainloop
    float* sX  = smem + OFF_X;
    float* sW1 = smem + OFF_W1;
    float* sB1 = smem + OFF_B1;
    float* sW2 = smem + OFF_W2;
    float* sB2 = smem + OFF_B2;

    const int tid  = threadIdx.x;
    const int lane = tid & 31, w = tid >> 5;
    const int tl = lane >> 2, iq = lane & 3;   // 8 t-lanes x 4 i-quarters
    const int t0 = blockIdx.x * TB_T;
    const int t  = t0 + tl;
    const bool tv = (t < D);
    const int Bb = blockIdx.y * TB_B;
    const int w8 = w * 8;                      // this thread's 8 b

    // ---- stage W0 tile, transposing [t][i][j] -> sW0[r][j][i], diag col zeroed ----
    for (int e = tid; e < 4096; e += NTH) {
        int i4 = e & 3, jql = (e >> 2) & 7, jqh = (e >> 5) & 3;
        int ih = (e >> 7) & 3, r = (e >> 9) & 7;
        int jq = jql + 8 * jqh, i = i4 + 4 * ih;
        if (jq < 25) {
            int tt = t0 + r;
            float4 v = make_float4(0.f, 0.f, 0.f, 0.f);
            if (tt < D) {
                v = *(const float4*)(W0g + ((size_t)(tt * H + i)) * D + 4 * jq);
                if ((tt >> 2) == jq) {   // fold (j != t) mask into weights
                    int c = tt & 3;
                    if (c == 0) v.x = 0.f;
                    else if (c == 1) v.y = 0.f;
                    else if (c == 2) v.z = 0.f;
                    else v.w = 0.f;
                }
            }
            float* dst = sW0 + r * W0S + i;
            dst[(4 * jq + 0) * 16] = v.x;
            dst[(4 * jq + 1) * 16] = v.y;
            dst[(4 * jq + 2) * 16] = v.z;
            dst[(4 * jq + 3) * 16] = v.w;
        }
    }
    // ---- stage x tile, transposing x[b][j] -> sX[j][b] ----
    for (int e = tid; e < 1600; e += NTH) {
        int b = e & 63, jq = e >> 6;
        float4 v = *(const float4*)(xg + (size_t)(Bb + b) * D + 4 * jq);
        sX[(4 * jq + 0) * 64 + b] = v.x;
        sX[(4 * jq + 1) * 64 + b] = v.y;
        sX[(4 * jq + 2) * 64 + b] = v.z;
        sX[(4 * jq + 3) * 64 + b] = v.w;
    }
    for (int e = tid; e < 8 * 256; e += NTH) {
        int r = e >> 8, c = e & 255;
        sW1[r * W1S + c] = (t0 + r < D) ? W1g[(t0 + r) * 256 + c] : 0.f;
    }
    if (tid < 128) {
        int r = tid >> 4, c = tid & 15;
        sB1[r * 17 + c] = (t0 + r < D) ? b1g[(t0 + r) * H + c] : 0.f;
    }
    if (tid < 256) {
        int r = tid >> 5, c = tid & 31;
        sW2[r * 36 + c] = (t0 + r < D) ? W2g[(t0 + r) * (P * H) + c] : 0.f;
    }
    if (tid < 16) {
        int r = tid >> 1, c = tid & 1;
        sB2[r * 2 + c] = (t0 + r < D) ? b2g[(t0 + r) * P + c] : 0.f;
    }
    __syncthreads();

    // ---- acc init with b0: acc[u][ip] ----
    ull acc[8][2];
    {
        int ib = 4 * iq;
        float a0 = tv ? __ldg(b0g + t * H + ib)     : 0.f;
        float a1 = tv ? __ldg(b0g + t * H + ib + 1) : 0.f;
        float a2 = tv ? __ldg(b0g + t * H + ib + 2) : 0.f;
        float a3 = tv ? __ldg(b0g + t * H + ib + 3) : 0.f;
        ull p0 = pk2(a0, a1), p1 = pk2(a2, a3);
#pragma unroll
        for (int u = 0; u < 8; ++u) { acc[u][0] = p0; acc[u][1] = p1; }
    }

    // ---- per-warp cp.async ring for m: 8 stages x 64 floats ----
    const float* ringf = smem + OFF_MR + w * 512;
    const unsigned ringu = smem_u32(ringf);
    const int ru = lane >> 2, rk2 = (lane & 3) * 2;      // lane's (b, t-pair) chunk
    const char* msrc0 =
        (const char*)(M + (size_t)(Bb + w8 + ru) * DD + t0 + rk2);
    const unsigned ssz = (t0 + rk2 < D) ? 8u : 0u;       // zero-fill OOB t (last tile)
    const unsigned sdst = ringu + (unsigned)lane * 8;

#define ISSUE_J(j)                                                              \
    {                                                                           \
        unsigned dst = sdst + (((j) & 7) << 8);                                 \
        const char* src = msrc0 + (size_t)(j) * (D * 4);                        \
        asm volatile(                                                           \
            "cp.async.ca.shared.global [%0], [%1], 8, %2;\n\t"                  \
            "cp.async.commit_group;"                                            \
            :: "r"(dst), "l"(src), "r"(ssz) : "memory");                        \
    }

#define COMP_J(j)                                                               \
    {                                                                           \
        const float* st = ringf + (((j) & 7) << 6);                             \
        longlong2 wq = *(const longlong2*)(sW0 + tl * W0S + (j) * 16 + iq * 4); \
        ull Wa = (ull)wq.x, Wb = (ull)wq.y;                                     \
        float4 xa = *(const float4*)(sX + (j) * 64 + w8);                       \
        float4 xb = *(const float4*)(sX + (j) * 64 + w8 + 4);                   \
        float xv[8] = {xa.x, xa.y, xa.z, xa.w, xb.x, xb.y, xb.z, xb.w};         \
        _Pragma("unroll")                                                       \
        for (int uu = 0; uu < 8; ++uu) {                                        \
            float mx = st[uu * 8 + tl] * xv[uu];                                \
            ull p = pk2(mx, mx);                                                \
            acc[uu][0] = ffma2(Wa, p, acc[uu][0]);                              \
            acc[uu][1] = ffma2(Wb, p, acc[uu][1]);                              \
        }                                                                       \
    }

#pragma unroll
    for (int j = 0; j < 7; ++j) ISSUE_J(j);
#pragma unroll 1
    for (int j = 0; j < 93; ++j) {
        ISSUE_J(j + 7);
        asm volatile("cp.async.wait_group 7;" ::: "memory");
        COMP_J(j);
    }
    asm volatile("cp.async.wait_group 0;" ::: "memory");
#pragma unroll
    for (int j = 93; j < 100; ++j) COMP_J(j);
#undef ISSUE_J
#undef COMP_J

    // ---- exchange h0 through smem (overlay on dead sW0) ----
    __syncthreads();
    {
        int ib = 4 * iq;
#pragma unroll
        for (int u = 0; u < 8; ++u) {
#pragma unroll
            for (int ip = 0; ip < 2; ++ip) {
                float a, b; unpk2(acc[u][ip], a, b);
                int i = ib + 2 * ip;
                sH0[tl * HS_T + i * HS_I + w8 + u]       = lrelu(a);
                sH0[tl * HS_T + (i + 1) * HS_I + w8 + u] = lrelu(b);
            }
        }
    }
    __syncthreads();

    // ---- layers 1 & 2: each thread handles 2 (t,b) pairs ----
#pragma unroll
    for (int rep = 0; rep < 2; ++rep) {
        int p = tid + rep * 256;
        int tloc = p >> 6, b = p & 63;
        int tg = t0 + tloc;
        float h0f[16];
#pragma unroll
        for (int i = 0; i < 16; ++i) h0f[i] = sH0[tloc * HS_T + i * HS_I + b];
        float h1[16];
#pragma unroll
        for (int ii = 0; ii < 16; ++ii) {
            const float4* w1r = (const float4*)(sW1 + tloc * W1S + ii * 16);
            float4 a = w1r[0], bb = w1r[1], c = w1r[2], d = w1r[3];
            float s = sB1[tloc * 17 + ii];
            s = fmaf(a.x,  h0f[0],  s); s = fmaf(a.y,  h0f[1],  s);
            s = fmaf(a.z,  h0f[2],  s); s = fmaf(a.w,  h0f[3],  s);
            s = fmaf(bb.x, h0f[4],  s); s = fmaf(bb.y, h0f[5],  s);
            s = fmaf(bb.z, h0f[6],  s); s = fmaf(bb.w, h0f[7],  s);
            s = fmaf(c.x,  h0f[8],  s); s = fmaf(c.y,  h0f[9],  s);
            s = fmaf(c.z,  h0f[10], s); s = fmaf(c.w,  h0f[11], s);
            s = fmaf(d.x,  h0f[12], s); s = fmaf(d.y,  h0f[13], s);
            s = fmaf(d.z,  h0f[14], s); s = fmaf(d.w,  h0f[15], s);
            h1[ii] = lrelu(s);
        }
        float po[2];
#pragma unroll
        for (int pp = 0; pp < 2; ++pp) {
            const float4* w2r = (const float4*)(sW2 + tloc * 36 + pp * 16);
            float4 a = w2r[0], bb = w2r[1], c = w2r[2], d = w2r[3];
            float s = sB2[tloc * 2 + pp];
            s = fmaf(a.x,  h1[0],  s); s = fmaf(a.y,  h1[1],  s);
            s = fmaf(a.z,  h1[2],  s); s = fmaf(a.w,  h1[3],  s);
            s = fmaf(bb.x, h1[4],  s); s = fmaf(bb.y, h1[5],  s);
            s = fmaf(bb.z, h1[6],  s); s = fmaf(bb.w, h1[7],  s);
            s = fmaf(c.x,  h1[8],  s); s = fmaf(c.y,  h1[9],  s);
            s = fmaf(c.z,  h1[10], s); s = fmaf(c.w,  h1[11], s);
            s = fmaf(d.x,  h1[12], s); s = fmaf(d.y,  h1[13], s);
            s = fmaf(d.z,  h1[14], s); s = fmaf(d.w,  h1[15], s);
            po[pp] = s;
        }
        if (tg < D) {
            float2 o = make_float2(po[0], po[1]);
            *(float2*)(out + ((size_t)(Bb + b) * D + tg) * P) = o;
        }
    }
}

extern "C" void kernel_launch(void* const* d_in, const int* in_sizes, int n_in,
                              void* d_out, int out_size) {
    const float* x  = (const float*)d_in[0];
    const float* M  = (const float*)d_in[1];
    const float* W0 = (const float*)d_in[2];
    const float* W1 = (const float*)d_in[3];
    const float* W2 = (const float*)d_in[4];
    const float* b0 = (const float*)d_in[5];
    const float* b1 = (const float*)d_in[6];
    const float* b2 = (const float*)d_in[7];
    float* out = (float*)d_out;

    constexpr int SMEM_BYTES = SMEM_FLOATS * 4;
    cudaFuncSetAttribute(mlp_kernel, cudaFuncAttributeMaxDynamicSharedMemorySize,
                         SMEM_BYTES);

    dim3 grid((D + TB_T - 1) / TB_T, BS / TB_B);   // 13 x 256, t fast
    mlp_kernel<<<grid, NTH, SMEM_BYTES>>>(x, M, W0, W1, W2, b0, b1, b2, out);
}